// round 4
// baseline (speedup 1.0000x reference)
#include <cuda_runtime.h>
#include <cuda_fp16.h>
#include <mma.h>

// Problem constants
#define BB 32
#define TT 256
#define EE 512
#define SS 5
#define VV 32000
#define MM (BB*TT)   // 8192 rows of zs
// GEMM tiling
#define BM 64
#define BN 128
#define BK 64
#define NCH (VV/BN)  // 250 vocab chunks
#define WPAD 72      // BK + 8 (half elements)
#define LPAD (BN+4)  // 132 (float elements)

using namespace nvcuda;

// ---------------- scratch (device globals; no allocation allowed) ----------------
__device__ __half d_Wv[(size_t)VV*EE];     // 32 MB  fp16 vocab weights
__device__ __half d_zs[(size_t)MM*EE];     // 8 MB   fp16 emitted states
__device__ float  d_pmax[(size_t)MM*NCH];  // 8 MB   per-tile max
__device__ float  d_psum[(size_t)MM*NCH];  // 8 MB   per-tile sumexp
__device__ float  d_yl[MM];                // fp32 logit at label

// ---------------- 1) convert W_vocab fp32 -> fp16 ----------------
__global__ void k_convert(const float* __restrict__ Wv) {
    int i = blockIdx.x * blockDim.x + threadIdx.x;
    int n = (VV * EE) / 4;
    if (i < n) {
        float4 v = ((const float4*)Wv)[i];
        ((__half2*)d_Wv)[2*i]   = __floats2half2_rn(v.x, v.y);
        ((__half2*)d_Wv)[2*i+1] = __floats2half2_rn(v.z, v.w);
    }
}

// ---------------- 2) recurrence: one CTA per batch, 512 threads ----------------
__global__ __launch_bounds__(512) void k_recur(
    const int*   __restrict__ zi,
    const float* __restrict__ latent,
    const float* __restrict__ W_tr,
    const float* __restrict__ b_tr,
    const float* __restrict__ W_ext,
    const float* __restrict__ b_ext)
{
    __shared__ float zn[EE];
    __shared__ float lat[4][EE];     // normalized latent rows s=1..4
    __shared__ float We[SS][EE];
    __shared__ float red5[16][6];
    __shared__ float att[8];
    __shared__ float bcast;

    const int b    = blockIdx.x;
    const int j    = threadIdx.x;
    const int wid  = j >> 5;
    const int lane = j & 31;
    const long base = (long)zi[b] * (SS * EE);

    #pragma unroll
    for (int s = 0; s < SS; s++) We[s][j] = W_ext[s * EE + j];

    // normalize the 5 latent rows (std with ddof=1)
    float zreg = 0.f;
    for (int s = 0; s < SS; s++) {
        float x = latent[base + s * EE + j];
        float s1 = x, s2 = x * x;
        #pragma unroll
        for (int o = 16; o > 0; o >>= 1) {
            s1 += __shfl_xor_sync(~0u, s1, o);
            s2 += __shfl_xor_sync(~0u, s2, o);
        }
        if (lane == 0) { red5[wid][0] = s1; red5[wid][1] = s2; }
        __syncthreads();
        if (j == 0) {
            float a = 0.f, c = 0.f;
            #pragma unroll
            for (int w = 0; w < 16; w++) { a += red5[w][0]; c += red5[w][1]; }
            float mean = a / EE;
            float var  = (c - EE * mean * mean) / (EE - 1);
            bcast = 0.113f / (1e-5f + sqrtf(fmaxf(var, 0.f)));
        }
        __syncthreads();
        float v = x * bcast;
        if (s == 0) zreg = v; else lat[s - 1][j] = v;
        __syncthreads();
    }
    const float bt = b_tr[j];

    for (int t = 0; t < TT; t++) {
        // zn = z / (1e-5 + std(z)) * 0.113
        float s1 = zreg, s2 = zreg * zreg;
        #pragma unroll
        for (int o = 16; o > 0; o >>= 1) {
            s1 += __shfl_xor_sync(~0u, s1, o);
            s2 += __shfl_xor_sync(~0u, s2, o);
        }
        if (lane == 0) { red5[wid][0] = s1; red5[wid][1] = s2; }
        __syncthreads();
        if (j == 0) {
            float a = 0.f, c = 0.f;
            #pragma unroll
            for (int w = 0; w < 16; w++) { a += red5[w][0]; c += red5[w][1]; }
            float mean = a / EE;
            float var  = (c - EE * mean * mean) / (EE - 1);
            bcast = 0.113f / (1e-5f + sqrtf(fmaxf(var, 0.f)));
        }
        __syncthreads();
        const float znj = zreg * bcast;
        zn[j] = znj;
        __syncthreads();

        // att[s] = dot(zn, W_ext[s]) + b_ext[s]
        float p[SS];
        #pragma unroll
        for (int s = 0; s < SS; s++) p[s] = znj * We[s][j];
        #pragma unroll
        for (int o = 16; o > 0; o >>= 1)
            #pragma unroll
            for (int s = 0; s < SS; s++) p[s] += __shfl_xor_sync(~0u, p[s], o);
        if (lane == 0)
            #pragma unroll
            for (int s = 0; s < SS; s++) red5[wid][s] = p[s];
        __syncthreads();
        if (j < SS) {
            float a = 0.f;
            #pragma unroll
            for (int w = 0; w < 16; w++) a += red5[w][j];
            att[j] = a + b_ext[j];
        }
        __syncthreads();

        // emit = att @ cand  (cand row 0 is zn, rows 1..4 are lat)
        float em = att[0] * znj + att[1] * lat[0][j] + att[2] * lat[1][j]
                 + att[3] * lat[2][j] + att[4] * lat[3][j];
        d_zs[((long)b * TT + t) * EE + j] = __float2half(em);

        // z_next[j] = (zn[j] + dot(zn, W_tr[j,:]) + b_tr[j]) / 2
        const float4* Wr = (const float4*)(W_tr + (long)j * EE);
        const float4* zv = (const float4*)zn;
        float acc = 0.f;
        #pragma unroll 8
        for (int k = 0; k < EE / 4; k++) {
            float4 w = Wr[k];
            float4 zq = zv[k];
            acc += w.x * zq.x + w.y * zq.y + w.z * zq.z + w.w * zq.w;
        }
        zreg = 0.5f * (znj + acc + bt);
        __syncthreads();   // protect zn / red5 / att / bcast before next iteration
    }
}

// ---------------- 3) fused vocab GEMM + per-tile (max, sumexp) ----------------
__global__ __launch_bounds__(256) void k_logits(const float* __restrict__ bvoc) {
    __shared__ __align__(16) unsigned char sm_raw[BM * LPAD * 4];  // 33792 B
    __half* As = (__half*)sm_raw;                      // BM x WPAD  (9216 B)
    __half* Bs = (__half*)(sm_raw + BM * WPAD * 2);    // BN x WPAD  (18432 B)
    float*  Ls = (float*)sm_raw;                       // BM x LPAD  (epilogue reuse)

    const int nch  = blockIdx.x;          // vocab chunk
    const int mch  = blockIdx.y;          // row chunk
    const int row0 = mch * BM;
    const int col0 = nch * BN;
    const int tid  = threadIdx.x;
    const int wid  = tid >> 5;            // 0..7
    const int wm   = wid >> 2;            // 0..1
    const int wn   = wid & 3;             // 0..3

    // loader indices: 8 uint4 segments per 64-half row, 32 rows per pass
    const int seg = tid & 7;              // 0..7  (seg*8 halves)
    const int lr0 = tid >> 3;             // 0..31

    wmma::fragment<wmma::accumulator, 16, 16, 16, float> c[2][2];
    #pragma unroll
    for (int i = 0; i < 2; i++)
        #pragma unroll
        for (int jj = 0; jj < 2; jj++) wmma::fill_fragment(c[i][jj], 0.f);

    for (int k0 = 0; k0 < EE; k0 += BK) {
        // A tile: 64 rows x 64 halves  (2 passes of 32 rows)
        #pragma unroll
        for (int rr = 0; rr < 2; rr++) {
            int row = lr0 + rr * 32;
            const uint4* src = (const uint4*)(d_zs + ((long)(row0 + row)) * EE + k0);
            ((uint4*)(As + row * WPAD))[seg] = src[seg];
        }
        // B tile: 128 rows x 64 halves (4 passes of 32 rows)
        #pragma unroll
        for (int rr = 0; rr < 4; rr++) {
            int row = lr0 + rr * 32;
            const uint4* src = (const uint4*)(d_Wv + ((long)(col0 + row)) * EE + k0);
            ((uint4*)(Bs + row * WPAD))[seg] = src[seg];
        }
        __syncthreads();
        #pragma unroll
        for (int kk = 0; kk < BK; kk += 16) {
            wmma::fragment<wmma::matrix_a, 16, 16, 16, __half, wmma::row_major> a[2];
            wmma::fragment<wmma::matrix_b, 16, 16, 16, __half, wmma::col_major> bf[2];
            #pragma unroll
            for (int i = 0; i < 2; i++)
                wmma::load_matrix_sync(a[i], As + (wm * 32 + i * 16) * WPAD + kk, WPAD);
            #pragma unroll
            for (int jj = 0; jj < 2; jj++)
                wmma::load_matrix_sync(bf[jj], Bs + (wn * 32 + jj * 16) * WPAD + kk, WPAD);
            #pragma unroll
            for (int i = 0; i < 2; i++)
                #pragma unroll
                for (int jj = 0; jj < 2; jj++)
                    wmma::mma_sync(c[i][jj], a[i], bf[jj], c[i][jj]);
        }
        __syncthreads();
    }

    // epilogue: spill tile to smem, per-row max & sumexp
    #pragma unroll
    for (int i = 0; i < 2; i++)
        #pragma unroll
        for (int jj = 0; jj < 2; jj++)
            wmma::store_matrix_sync(Ls + (wm * 32 + i * 16) * LPAD + wn * 32 + jj * 16,
                                    c[i][jj], LPAD, wmma::mem_row_major);
    __syncthreads();

    const int r = tid >> 2, q = tid & 3;   // 4 threads per row
    const float* lrp = Ls + r * LPAD;
    float mx = -1e30f;
    for (int cix = q * 32; cix < q * 32 + 32; cix++) {
        float v = lrp[cix] + bvoc[col0 + cix];
        mx = fmaxf(mx, v);
    }
    mx = fmaxf(mx, __shfl_xor_sync(~0u, mx, 1));
    mx = fmaxf(mx, __shfl_xor_sync(~0u, mx, 2));
    float sum = 0.f;
    for (int cix = q * 32; cix < q * 32 + 32; cix++) {
        float v = lrp[cix] + bvoc[col0 + cix];
        sum += __expf(v - mx);
    }
    sum += __shfl_xor_sync(~0u, sum, 1);
    sum += __shfl_xor_sync(~0u, sum, 2);
    if (q == 0) {
        d_pmax[(long)(row0 + r) * NCH + nch] = mx;
        d_psum[(long)(row0 + r) * NCH + nch] = sum;
    }
}

// ---------------- 4) exact logit at label (fp32 weights, fp16 zs) ----------------
__global__ void k_ylogit(const int* __restrict__ y,
                         const float* __restrict__ Wv,
                         const float* __restrict__ bvoc) {
    int r = blockIdx.x * 8 + (threadIdx.x >> 5);
    int lane = threadIdx.x & 31;
    int yv = y[r];
    const __half* z = d_zs + (long)r * EE;
    const float*  w = Wv + (long)yv * EE;
    float acc = 0.f;
    for (int e = lane; e < EE; e += 32)
        acc += __half2float(z[e]) * w[e];
    #pragma unroll
    for (int o = 16; o > 0; o >>= 1) acc += __shfl_xor_sync(~0u, acc, o);
    if (lane == 0) d_yl[r] = acc + bvoc[yv];
}

// ---------------- 5) combine partials: yp = logit[y] - logsumexp ----------------
__global__ __launch_bounds__(256) void k_final(float* __restrict__ out) {
    const int r = blockIdx.x;
    const int tid = threadIdx.x;
    __shared__ float sm[8];
    __shared__ float Mx;
    float m = -1e30f;
    for (int c = tid; c < NCH; c += 256) m = fmaxf(m, d_pmax[(long)r * NCH + c]);
    #pragma unroll
    for (int o = 16; o > 0; o >>= 1) m = fmaxf(m, __shfl_xor_sync(~0u, m, o));
    if ((tid & 31) == 0) sm[tid >> 5] = m;
    __syncthreads();
    if (tid == 0) {
        float a = -1e30f;
        #pragma unroll
        for (int w = 0; w < 8; w++) a = fmaxf(a, sm[w]);
        Mx = a;
    }
    __syncthreads();
    float s = 0.f;
    for (int c = tid; c < NCH; c += 256)
        s += d_psum[(long)r * NCH + c] * __expf(d_pmax[(long)r * NCH + c] - Mx);
    #pragma unroll
    for (int o = 16; o > 0; o >>= 1) s += __shfl_xor_sync(~0u, s, o);
    if ((tid & 31) == 0) sm[tid >> 5] = s;
    __syncthreads();
    if (tid == 0) {
        float a = 0.f;
        #pragma unroll
        for (int w = 0; w < 8; w++) a += sm[w];
        out[r] = d_yl[r] - (Mx + logf(a));
    }
}

// ---------------- launch ----------------
extern "C" void kernel_launch(void* const* d_in, const int* in_sizes, int n_in,
                              void* d_out, int out_size) {
    const int*   zi     = (const int*)d_in[0];
    const int*   y      = (const int*)d_in[1];
    const float* latent = (const float*)d_in[2];
    const float* W_tr   = (const float*)d_in[3];
    const float* b_tr   = (const float*)d_in[4];
    const float* Wv     = (const float*)d_in[5];
    const float* bvoc   = (const float*)d_in[6];
    const float* W_ext  = (const float*)d_in[7];
    const float* b_ext  = (const float*)d_in[8];
    float* out = (float*)d_out;

    k_convert<<<(VV * EE / 4 + 255) / 256, 256>>>(Wv);
    k_recur<<<BB, 512>>>(zi, latent, W_tr, b_tr, W_ext, b_ext);
    k_ylogit<<<MM / 8, 256>>>(y, Wv, bvoc);
    k_logits<<<dim3(NCH, MM / BM), 256>>>(bvoc);
    k_final<<<MM, 256>>>(out);
}

// round 5
// speedup vs baseline: 2.8800x; 2.8800x over previous
#include <cuda_runtime.h>
#include <cuda_fp16.h>
#include <mma.h>

// Problem constants
#define BB 32
#define TT 256
#define EE 512
#define SS 5
#define VV 32000
#define MM (BB*TT)   // 8192 rows of zs
// GEMM tiling
#define BM 64
#define BN 128
#define BK 64
#define NCH (VV/BN)  // 250 vocab chunks
#define WPAD 72      // BK + 8 (half elements)
#define LPAD (BN+4)  // 132 (float elements)

using namespace nvcuda;

// ---------------- scratch (device globals; no allocation allowed) ----------------
__device__ __half d_Wv[(size_t)VV*EE];     // 32 MB  fp16 vocab weights
__device__ __half d_zs[(size_t)MM*EE];     // 8 MB   fp16 emitted states
__device__ float  d_pmax[(size_t)MM*NCH];  // 8 MB   per-tile max
__device__ float  d_psum[(size_t)MM*NCH];  // 8 MB   per-tile sumexp
__device__ float  d_yl[MM];                // fp32 logit at label

// ---------------- 1) convert W_vocab fp32 -> fp16 ----------------
__global__ void k_convert(const float* __restrict__ Wv) {
    int i = blockIdx.x * blockDim.x + threadIdx.x;
    int n = (VV * EE) / 4;
    if (i < n) {
        float4 v = ((const float4*)Wv)[i];
        ((__half2*)d_Wv)[2*i]   = __floats2half2_rn(v.x, v.y);
        ((__half2*)d_Wv)[2*i+1] = __floats2half2_rn(v.z, v.w);
    }
}

// ---------------- 2) recurrence: one CTA per batch, 512 threads ----------------
// Matvec layout: warp w computes output rows [32w, 32w+32). For each row the 32
// lanes read CONTIGUOUS float4s of W_tr (coalesced; 4 wavefronts per LDG.128
// instead of 32 with the old row-per-thread layout) and shfl-reduce.
__global__ __launch_bounds__(512) void k_recur(
    const int*   __restrict__ zi,
    const float* __restrict__ latent,
    const float* __restrict__ W_tr,
    const float* __restrict__ b_tr,
    const float* __restrict__ W_ext,
    const float* __restrict__ b_ext)
{
    __shared__ float zbuf[EE];       // pre-norm recurrent state z
    __shared__ float zn[EE];         // normalized state
    __shared__ float lat[4][EE];     // normalized latent rows s=1..4
    __shared__ float We[SS][EE];
    __shared__ float bts[EE];
    __shared__ float red5[16][6];
    __shared__ float att[8];
    __shared__ float bcast;

    const int b    = blockIdx.x;
    const int j    = threadIdx.x;
    const int wid  = j >> 5;
    const int lane = j & 31;
    const long base = (long)zi[b] * (SS * EE);

    #pragma unroll
    for (int s = 0; s < SS; s++) We[s][j] = W_ext[s * EE + j];
    bts[j] = b_tr[j];

    // normalize the 5 latent rows (std with ddof=1)
    for (int s = 0; s < SS; s++) {
        float x = latent[base + s * EE + j];
        float s1 = x, s2 = x * x;
        #pragma unroll
        for (int o = 16; o > 0; o >>= 1) {
            s1 += __shfl_xor_sync(~0u, s1, o);
            s2 += __shfl_xor_sync(~0u, s2, o);
        }
        if (lane == 0) { red5[wid][0] = s1; red5[wid][1] = s2; }
        __syncthreads();
        if (j == 0) {
            float a = 0.f, c = 0.f;
            #pragma unroll
            for (int w = 0; w < 16; w++) { a += red5[w][0]; c += red5[w][1]; }
            float mean = a / EE;
            float var  = (c - EE * mean * mean) / (EE - 1);
            bcast = 0.113f / (1e-5f + sqrtf(fmaxf(var, 0.f)));
        }
        __syncthreads();
        float v = x * bcast;
        if (s == 0) zbuf[j] = v; else lat[s - 1][j] = v;
        __syncthreads();
    }

    for (int t = 0; t < TT; t++) {
        // zn = z / (1e-5 + std(z)) * 0.113
        float zj = zbuf[j];
        float s1 = zj, s2 = zj * zj;
        #pragma unroll
        for (int o = 16; o > 0; o >>= 1) {
            s1 += __shfl_xor_sync(~0u, s1, o);
            s2 += __shfl_xor_sync(~0u, s2, o);
        }
        if (lane == 0) { red5[wid][0] = s1; red5[wid][1] = s2; }
        __syncthreads();
        if (j == 0) {
            float a = 0.f, c = 0.f;
            #pragma unroll
            for (int w = 0; w < 16; w++) { a += red5[w][0]; c += red5[w][1]; }
            float mean = a / EE;
            float var  = (c - EE * mean * mean) / (EE - 1);
            bcast = 0.113f / (1e-5f + sqrtf(fmaxf(var, 0.f)));
        }
        __syncthreads();
        const float znj = zj * bcast;
        zn[j] = znj;
        __syncthreads();

        // att[s] = dot(zn, W_ext[s]) + b_ext[s]
        float p[SS];
        #pragma unroll
        for (int s = 0; s < SS; s++) p[s] = znj * We[s][j];
        #pragma unroll
        for (int o = 16; o > 0; o >>= 1)
            #pragma unroll
            for (int s = 0; s < SS; s++) p[s] += __shfl_xor_sync(~0u, p[s], o);
        if (lane == 0)
            #pragma unroll
            for (int s = 0; s < SS; s++) red5[wid][s] = p[s];
        __syncthreads();
        if (j < SS) {
            float a = 0.f;
            #pragma unroll
            for (int w = 0; w < 16; w++) a += red5[w][j];
            att[j] = a + b_ext[j];
        }
        __syncthreads();

        // emit = att @ cand  (cand row 0 is zn, rows 1..4 are lat)
        float em = att[0] * znj + att[1] * lat[0][j] + att[2] * lat[1][j]
                 + att[3] * lat[2][j] + att[4] * lat[3][j];
        d_zs[((long)b * TT + t) * EE + j] = __float2half(em);

        // z_next[r] = (zn[r] + dot(zn, W_tr[r,:]) + b_tr[r]) / 2
        // warp w owns rows [32w, 32w+32); coalesced W loads + shfl reduce.
        float4 zf[4];
        const float4* znv = (const float4*)zn;
        #pragma unroll
        for (int k = 0; k < 4; k++) zf[k] = znv[k * 32 + lane];

        const int rbase = wid * 32;
        #pragma unroll 4
        for (int rr = 0; rr < 32; rr++) {
            const int r = rbase + rr;
            const float4* Wr = (const float4*)(W_tr + (long)r * EE);
            float acc = 0.f;
            #pragma unroll
            for (int k = 0; k < 4; k++) {
                float4 w = Wr[k * 32 + lane];
                acc += w.x * zf[k].x + w.y * zf[k].y + w.z * zf[k].z + w.w * zf[k].w;
            }
            #pragma unroll
            for (int o = 16; o > 0; o >>= 1) acc += __shfl_xor_sync(~0u, acc, o);
            if (lane == 0) zbuf[r] = 0.5f * (zn[r] + acc + bts[r]);
        }
        __syncthreads();   // zbuf ready; also protects zn/red5/att/bcast reuse
    }
}

// ---------------- 3) fused vocab GEMM + per-tile (max, sumexp) ----------------
__global__ __launch_bounds__(256) void k_logits(const float* __restrict__ bvoc) {
    __shared__ __align__(16) unsigned char sm_raw[BM * LPAD * 4];  // 33792 B
    __half* As = (__half*)sm_raw;                      // BM x WPAD  (9216 B)
    __half* Bs = (__half*)(sm_raw + BM * WPAD * 2);    // BN x WPAD  (18432 B)
    float*  Ls = (float*)sm_raw;                       // BM x LPAD  (epilogue reuse)

    const int nch  = blockIdx.x;          // vocab chunk
    const int mch  = blockIdx.y;          // row chunk
    const int row0 = mch * BM;
    const int col0 = nch * BN;
    const int tid  = threadIdx.x;
    const int wid  = tid >> 5;            // 0..7
    const int wm   = wid >> 2;            // 0..1
    const int wn   = wid & 3;             // 0..3

    // loader indices: 8 uint4 segments per 64-half row, 32 rows per pass
    const int seg = tid & 7;              // 0..7  (seg*8 halves)
    const int lr0 = tid >> 3;             // 0..31

    wmma::fragment<wmma::accumulator, 16, 16, 16, float> c[2][2];
    #pragma unroll
    for (int i = 0; i < 2; i++)
        #pragma unroll
        for (int jj = 0; jj < 2; jj++) wmma::fill_fragment(c[i][jj], 0.f);

    for (int k0 = 0; k0 < EE; k0 += BK) {
        // A tile: 64 rows x 64 halves  (2 passes of 32 rows)
        #pragma unroll
        for (int rr = 0; rr < 2; rr++) {
            int row = lr0 + rr * 32;
            const uint4* src = (const uint4*)(d_zs + ((long)(row0 + row)) * EE + k0);
            ((uint4*)(As + row * WPAD))[seg] = src[seg];
        }
        // B tile: 128 rows x 64 halves (4 passes of 32 rows)
        #pragma unroll
        for (int rr = 0; rr < 4; rr++) {
            int row = lr0 + rr * 32;
            const uint4* src = (const uint4*)(d_Wv + ((long)(col0 + row)) * EE + k0);
            ((uint4*)(Bs + row * WPAD))[seg] = src[seg];
        }
        __syncthreads();
        #pragma unroll
        for (int kk = 0; kk < BK; kk += 16) {
            wmma::fragment<wmma::matrix_a, 16, 16, 16, __half, wmma::row_major> a[2];
            wmma::fragment<wmma::matrix_b, 16, 16, 16, __half, wmma::col_major> bf[2];
            #pragma unroll
            for (int i = 0; i < 2; i++)
                wmma::load_matrix_sync(a[i], As + (wm * 32 + i * 16) * WPAD + kk, WPAD);
            #pragma unroll
            for (int jj = 0; jj < 2; jj++)
                wmma::load_matrix_sync(bf[jj], Bs + (wn * 32 + jj * 16) * WPAD + kk, WPAD);
            #pragma unroll
            for (int i = 0; i < 2; i++)
                #pragma unroll
                for (int jj = 0; jj < 2; jj++)
                    wmma::mma_sync(c[i][jj], a[i], bf[jj], c[i][jj]);
        }
        __syncthreads();
    }

    // epilogue: spill tile to smem, per-row max & sumexp
    #pragma unroll
    for (int i = 0; i < 2; i++)
        #pragma unroll
        for (int jj = 0; jj < 2; jj++)
            wmma::store_matrix_sync(Ls + (wm * 32 + i * 16) * LPAD + wn * 32 + jj * 16,
                                    c[i][jj], LPAD, wmma::mem_row_major);
    __syncthreads();

    const int r = tid >> 2, q = tid & 3;   // 4 threads per row
    const float* lrp = Ls + r * LPAD;
    float mx = -1e30f;
    for (int cix = q * 32; cix < q * 32 + 32; cix++) {
        float v = lrp[cix] + bvoc[col0 + cix];
        mx = fmaxf(mx, v);
    }
    mx = fmaxf(mx, __shfl_xor_sync(~0u, mx, 1));
    mx = fmaxf(mx, __shfl_xor_sync(~0u, mx, 2));
    float sum = 0.f;
    for (int cix = q * 32; cix < q * 32 + 32; cix++) {
        float v = lrp[cix] + bvoc[col0 + cix];
        sum += __expf(v - mx);
    }
    sum += __shfl_xor_sync(~0u, sum, 1);
    sum += __shfl_xor_sync(~0u, sum, 2);
    if (q == 0) {
        d_pmax[(long)(row0 + r) * NCH + nch] = mx;
        d_psum[(long)(row0 + r) * NCH + nch] = sum;
    }
}

// ---------------- 4) exact logit at label (fp32 weights, fp16 zs) ----------------
__global__ void k_ylogit(const int* __restrict__ y,
                         const float* __restrict__ Wv,
                         const float* __restrict__ bvoc) {
    int r = blockIdx.x * 8 + (threadIdx.x >> 5);
    int lane = threadIdx.x & 31;
    int yv = y[r];
    const __half* z = d_zs + (long)r * EE;
    const float*  w = Wv + (long)yv * EE;
    float acc = 0.f;
    for (int e = lane; e < EE; e += 32)
        acc += __half2float(z[e]) * w[e];
    #pragma unroll
    for (int o = 16; o > 0; o >>= 1) acc += __shfl_xor_sync(~0u, acc, o);
    if (lane == 0) d_yl[r] = acc + bvoc[yv];
}

// ---------------- 5) combine partials: yp = logit[y] - logsumexp ----------------
__global__ __launch_bounds__(256) void k_final(float* __restrict__ out) {
    const int r = blockIdx.x;
    const int tid = threadIdx.x;
    __shared__ float sm[8];
    __shared__ float Mx;
    float m = -1e30f;
    for (int c = tid; c < NCH; c += 256) m = fmaxf(m, d_pmax[(long)r * NCH + c]);
    #pragma unroll
    for (int o = 16; o > 0; o >>= 1) m = fmaxf(m, __shfl_xor_sync(~0u, m, o));
    if ((tid & 31) == 0) sm[tid >> 5] = m;
    __syncthreads();
    if (tid == 0) {
        float a = -1e30f;
        #pragma unroll
        for (int w = 0; w < 8; w++) a = fmaxf(a, sm[w]);
        Mx = a;
    }
    __syncthreads();
    float s = 0.f;
    for (int c = tid; c < NCH; c += 256)
        s += d_psum[(long)r * NCH + c] * __expf(d_pmax[(long)r * NCH + c] - Mx);
    #pragma unroll
    for (int o = 16; o > 0; o >>= 1) s += __shfl_xor_sync(~0u, s, o);
    if ((tid & 31) == 0) sm[tid >> 5] = s;
    __syncthreads();
    if (tid == 0) {
        float a = 0.f;
        #pragma unroll
        for (int w = 0; w < 8; w++) a += sm[w];
        out[r] = d_yl[r] - (Mx + logf(a));
    }
}

// ---------------- launch ----------------
extern "C" void kernel_launch(void* const* d_in, const int* in_sizes, int n_in,
                              void* d_out, int out_size) {
    const int*   zi     = (const int*)d_in[0];
    const int*   y      = (const int*)d_in[1];
    const float* latent = (const float*)d_in[2];
    const float* W_tr   = (const float*)d_in[3];
    const float* b_tr   = (const float*)d_in[4];
    const float* Wv     = (const float*)d_in[5];
    const float* bvoc   = (const float*)d_in[6];
    const float* W_ext  = (const float*)d_in[7];
    const float* b_ext  = (const float*)d_in[8];
    float* out = (float*)d_out;

    k_convert<<<(VV * EE / 4 + 255) / 256, 256>>>(Wv);
    k_recur<<<BB, 512>>>(zi, latent, W_tr, b_tr, W_ext, b_ext);
    k_ylogit<<<MM / 8, 256>>>(y, Wv, bvoc);
    k_logits<<<dim3(NCH, MM / BM), 256>>>(bvoc);
    k_final<<<MM, 256>>>(out);
}

// round 8
// speedup vs baseline: 3.6057x; 1.2520x over previous
#include <cuda_runtime.h>
#include <cuda_fp16.h>
#include <cstdint>
#include <mma.h>

// Problem constants
#define BB 32
#define TT 256
#define EE 512
#define SS 5
#define VV 32000
#define MM (BB*TT)   // 8192 rows of zs
// Recurrence cluster config
#define RCTA 4
#define RTHREADS 256
#define RROWS (EE/RCTA)      // 128 rows per CTA
// GEMM tiling
#define BM 128
#define BN 128
#define BK 64
#define NCH (VV/BN)  // 250 vocab chunks
#define WPAD 72      // BK + 8 (half elements)
#define LPAD (BN+4)  // 132 (float elements)

using namespace nvcuda;

// ---------------- scratch (device globals; no allocation allowed) ----------------
__device__ __half d_Wv[(size_t)VV*EE];     // 32 MB  fp16 vocab weights
__device__ __half d_zs[(size_t)MM*EE];     // 8 MB   fp16 emitted states
__device__ float  d_pmax[(size_t)MM*NCH];  // 8 MB   per-tile max
__device__ float  d_psum[(size_t)MM*NCH];  // 8 MB   per-tile sumexp
__device__ float  d_yl[MM];                // fp32 logit at label

// ---------------- 1) convert W_vocab fp32 -> fp16 ----------------
__global__ void k_convert(const float* __restrict__ Wv) {
    int i = blockIdx.x * blockDim.x + threadIdx.x;
    int n = (VV * EE) / 4;
    if (i < n) {
        float4 v = ((const float4*)Wv)[i];
        ((__half2*)d_Wv)[2*i]   = __floats2half2_rn(v.x, v.y);
        ((__half2*)d_Wv)[2*i+1] = __floats2half2_rn(v.z, v.w);
    }
}

// DSMEM store to a given cluster rank's smem at the same offset
__device__ __forceinline__ void st_cluster_f32(uint32_t laddr, int rank, float v) {
    uint32_t ra;
    asm volatile("mapa.shared::cluster.u32 %0, %1, %2;" : "=r"(ra) : "r"(laddr), "r"(rank));
    asm volatile("st.shared::cluster.f32 [%0], %1;" :: "r"(ra), "f"(v) : "memory");
}

// ---------------- 2) recurrence: 4-CTA cluster per batch ----------------
// Each CTA owns output rows [rank*128, rank*128+128) of the matvec (streams a
// 256KB W_tr slice -> 2048 L1 wavefronts/step). Small ops (std, att, emit) are
// computed redundantly from a replicated state copy. z_next chunks are pushed
// to all 4 CTAs' ping-pong zbuf via DSMEM; one cluster.sync per step.
__global__ __launch_bounds__(RTHREADS) __cluster_dims__(RCTA, 1, 1)
void k_recur(
    const int*   __restrict__ zi,
    const float* __restrict__ latent,
    const float* __restrict__ W_tr,
    const float* __restrict__ b_tr,
    const float* __restrict__ W_ext,
    const float* __restrict__ b_ext)
{
    __shared__ float zbuf[2][EE];        // ping-pong replicated state
    __shared__ float zn[EE];             // normalized state (replicated)
    __shared__ float latsl[4][RROWS];    // lat rows 1..4, own slice only
    __shared__ float We[SS][EE];
    __shared__ float btsl[RROWS];
    __shared__ float red[8][6];
    __shared__ float att[8];
    __shared__ float bcast;

    const int tid  = threadIdx.x;
    const int wid  = tid >> 5;
    const int lane = tid & 31;
    const int b    = blockIdx.x / RCTA;
    const int rank = blockIdx.x % RCTA;
    const long base = (long)zi[b] * (SS * EE);

    #pragma unroll
    for (int s = 0; s < SS; s++) {
        We[s][tid]       = W_ext[s * EE + tid];
        We[s][tid + 256] = W_ext[s * EE + tid + 256];
    }
    if (tid < RROWS) btsl[tid] = b_tr[rank * RROWS + tid];

    // normalize the 5 latent rows (std with ddof=1); full row redundantly
    for (int s = 0; s < SS; s++) {
        float x0 = latent[base + s * EE + tid];
        float x1 = latent[base + s * EE + tid + 256];
        float s1 = x0 + x1, s2 = x0 * x0 + x1 * x1;
        #pragma unroll
        for (int o = 16; o > 0; o >>= 1) {
            s1 += __shfl_xor_sync(~0u, s1, o);
            s2 += __shfl_xor_sync(~0u, s2, o);
        }
        if (lane == 0) { red[wid][0] = s1; red[wid][1] = s2; }
        __syncthreads();
        if (tid == 0) {
            float a = 0.f, c = 0.f;
            #pragma unroll
            for (int w = 0; w < 8; w++) { a += red[w][0]; c += red[w][1]; }
            float mean = a / EE;
            float var  = (c - EE * mean * mean) / (EE - 1);
            bcast = 0.113f / (1e-5f + sqrtf(fmaxf(var, 0.f)));
        }
        __syncthreads();
        float v0 = x0 * bcast, v1 = x1 * bcast;
        if (s == 0) {
            zbuf[0][tid] = v0; zbuf[0][tid + 256] = v1;
        } else {
            zn[tid] = v0; zn[tid + 256] = v1;   // scratch
            __syncthreads();
            if (tid < RROWS) latsl[s - 1][tid] = zn[rank * RROWS + tid];
        }
        __syncthreads();
    }

    const uint32_t zb0 = (uint32_t)__cvta_generic_to_shared(&zbuf[0][0]);
    const uint32_t zb1 = (uint32_t)__cvta_generic_to_shared(&zbuf[1][0]);

    for (int t = 0; t < TT; t++) {
        const int cur = t & 1;
        const float z0 = zbuf[cur][tid], z1 = zbuf[cur][tid + 256];

        // std(z)
        float s1 = z0 + z1, s2 = z0 * z0 + z1 * z1;
        #pragma unroll
        for (int o = 16; o > 0; o >>= 1) {
            s1 += __shfl_xor_sync(~0u, s1, o);
            s2 += __shfl_xor_sync(~0u, s2, o);
        }
        if (lane == 0) { red[wid][0] = s1; red[wid][1] = s2; }
        __syncthreads();
        if (tid == 0) {
            float a = 0.f, c = 0.f;
            #pragma unroll
            for (int w = 0; w < 8; w++) { a += red[w][0]; c += red[w][1]; }
            float mean = a / EE;
            float var  = (c - EE * mean * mean) / (EE - 1);
            bcast = 0.113f / (1e-5f + sqrtf(fmaxf(var, 0.f)));
        }
        __syncthreads();
        const float zn0 = z0 * bcast, zn1 = z1 * bcast;
        zn[tid] = zn0; zn[tid + 256] = zn1;

        // att[s] = dot(zn, W_ext[s]) + b_ext[s]  (redundant per CTA)
        float p[SS];
        #pragma unroll
        for (int s = 0; s < SS; s++) p[s] = zn0 * We[s][tid] + zn1 * We[s][tid + 256];
        #pragma unroll
        for (int o = 16; o > 0; o >>= 1)
            #pragma unroll
            for (int s = 0; s < SS; s++) p[s] += __shfl_xor_sync(~0u, p[s], o);
        if (lane == 0)
            #pragma unroll
            for (int s = 0; s < SS; s++) red[wid][s] = p[s];
        __syncthreads();
        if (tid < SS) {
            float a = 0.f;
            #pragma unroll
            for (int w = 0; w < 8; w++) a += red[w][tid];
            att[tid] = a + b_ext[tid];
        }
        __syncthreads();   // zn + att visible

        // emit: own 128-element slice only
        if (tid < RROWS) {
            const int jg = rank * RROWS + tid;
            float em = att[0] * zn[jg] + att[1] * latsl[0][tid] + att[2] * latsl[1][tid]
                     + att[3] * latsl[2][tid] + att[4] * latsl[3][tid];
            d_zs[((long)b * TT + t) * EE + jg] = __float2half(em);
        }

        // matvec rows [rank*128, rank*128+128): warp w -> 16 rows
        float4 zf[4];
        const float4* znv = (const float4*)zn;
        #pragma unroll
        for (int k = 0; k < 4; k++) zf[k] = znv[k * 32 + lane];

        const uint32_t zbn = (t & 1) ? zb0 : zb1;   // next buffer
        const int rbase = rank * RROWS + wid * 16;
        #pragma unroll 4
        for (int rr = 0; rr < 16; rr++) {
            const int r = rbase + rr;
            const float4* Wr = (const float4*)(W_tr + (long)r * EE);
            float acc = 0.f;
            #pragma unroll
            for (int k = 0; k < 4; k++) {
                float4 w = Wr[k * 32 + lane];
                acc += w.x * zf[k].x + w.y * zf[k].y + w.z * zf[k].z + w.w * zf[k].w;
            }
            #pragma unroll
            for (int o = 16; o > 0; o >>= 1) acc += __shfl_xor_sync(~0u, acc, o);
            if (lane == 0) {
                float v = 0.5f * (zn[r] + acc + btsl[wid * 16 + rr]);
                uint32_t la = zbn + (uint32_t)(r * 4);
                #pragma unroll
                for (int pp = 0; pp < RCTA; pp++) st_cluster_f32(la, pp, v);
            }
        }

        // one cluster barrier per step (release/acquire orders DSMEM stores)
        asm volatile("barrier.cluster.arrive.aligned;" ::: "memory");
        asm volatile("barrier.cluster.wait.aligned;" ::: "memory");
    }
}

// ---------------- 3) fused vocab GEMM + per-tile (max, sumexp) ----------------
// BM=128, BN=128, BK=64; 8 warps in 2(m)x4(n), warp tile 64x32.
__global__ __launch_bounds__(256, 2) void k_logits(const float* __restrict__ bvoc) {
    __shared__ __align__(16) unsigned char sm_raw[2 * BM * WPAD * 2];  // 36864 B
    __half* As = (__half*)sm_raw;                      // BM x WPAD
    __half* Bs = (__half*)(sm_raw + BM * WPAD * 2);    // BN x WPAD
    float*  Ls = (float*)sm_raw;                       // 64 x LPAD epilogue (33792 B)

    const int nch  = blockIdx.x;
    const int mch  = blockIdx.y;
    const int row0 = mch * BM;
    const int col0 = nch * BN;
    const int tid  = threadIdx.x;
    const int wid  = tid >> 5;            // 0..7
    const int wm   = wid >> 2;            // 0..1  (64-row group)
    const int wn   = wid & 3;             // 0..3  (32-col group)

    // loader indices: 8 uint4 segments per 64-half row, 32 rows per pass
    const int seg = tid & 7;
    const int lr0 = tid >> 3;             // 0..31

    wmma::fragment<wmma::accumulator, 16, 16, 16, float> c[4][2];
    #pragma unroll
    for (int i = 0; i < 4; i++)
        #pragma unroll
        for (int jj = 0; jj < 2; jj++) wmma::fill_fragment(c[i][jj], 0.f);

    for (int k0 = 0; k0 < EE; k0 += BK) {
        // A tile: 128 rows (4 passes of 32)
        #pragma unroll
        for (int rr = 0; rr < 4; rr++) {
            int row = lr0 + rr * 32;
            const uint4* src = (const uint4*)(d_zs + ((long)(row0 + row)) * EE + k0);
            ((uint4*)(As + row * WPAD))[seg] = src[seg];
        }
        // B tile: 128 rows (4 passes of 32)
        #pragma unroll
        for (int rr = 0; rr < 4; rr++) {
            int row = lr0 + rr * 32;
            const uint4* src = (const uint4*)(d_Wv + ((long)(col0 + row)) * EE + k0);
            ((uint4*)(Bs + row * WPAD))[seg] = src[seg];
        }
        __syncthreads();
        #pragma unroll
        for (int kk = 0; kk < BK; kk += 16) {
            wmma::fragment<wmma::matrix_b, 16, 16, 16, __half, wmma::col_major> bf[2];
            #pragma unroll
            for (int jj = 0; jj < 2; jj++)
                wmma::load_matrix_sync(bf[jj], Bs + (wn * 32 + jj * 16) * WPAD + kk, WPAD);
            #pragma unroll
            for (int i = 0; i < 4; i++) {
                wmma::fragment<wmma::matrix_a, 16, 16, 16, __half, wmma::row_major> a;
                wmma::load_matrix_sync(a, As + (wm * 64 + i * 16) * WPAD + kk, WPAD);
                #pragma unroll
                for (int jj = 0; jj < 2; jj++)
                    wmma::mma_sync(c[i][jj], a, bf[jj], c[i][jj]);
            }
        }
        __syncthreads();
    }

    // epilogue: two passes of 64 rows through smem
    #pragma unroll
    for (int pass = 0; pass < 2; pass++) {
        __syncthreads();
        if (wm == pass) {
            #pragma unroll
            for (int i = 0; i < 4; i++)
                #pragma unroll
                for (int jj = 0; jj < 2; jj++)
                    wmma::store_matrix_sync(Ls + (i * 16) * LPAD + wn * 32 + jj * 16,
                                            c[i][jj], LPAD, wmma::mem_row_major);
        }
        __syncthreads();

        const int r = tid >> 2, q = tid & 3;    // 64 rows x 4 threads
        const float* lrp = Ls + r * LPAD;
        float mx = -1e30f;
        for (int cix = q * 32; cix < q * 32 + 32; cix++) {
            float v = lrp[cix] + bvoc[col0 + cix];
            mx = fmaxf(mx, v);
        }
        mx = fmaxf(mx, __shfl_xor_sync(~0u, mx, 1));
        mx = fmaxf(mx, __shfl_xor_sync(~0u, mx, 2));
        float sum = 0.f;
        for (int cix = q * 32; cix < q * 32 + 32; cix++) {
            float v = lrp[cix] + bvoc[col0 + cix];
            sum += __expf(v - mx);
        }
        sum += __shfl_xor_sync(~0u, sum, 1);
        sum += __shfl_xor_sync(~0u, sum, 2);
        if (q == 0) {
            const long grow = row0 + pass * 64 + r;
            d_pmax[grow * NCH + nch] = mx;
            d_psum[grow * NCH + nch] = sum;
        }
    }
}

// ---------------- 4) exact logit at label (fp32 weights, fp16 zs) ----------------
__global__ void k_ylogit(const int* __restrict__ y,
                         const float* __restrict__ Wv,
                         const float* __restrict__ bvoc) {
    int r = blockIdx.x * 8 + (threadIdx.x >> 5);
    int lane = threadIdx.x & 31;
    int yv = y[r];
    const __half* z = d_zs + (long)r * EE;
    const float*  w = Wv + (long)yv * EE;
    float acc = 0.f;
    for (int e = lane; e < EE; e += 32)
        acc += __half2float(z[e]) * w[e];
    #pragma unroll
    for (int o = 16; o > 0; o >>= 1) acc += __shfl_xor_sync(~0u, acc, o);
    if (lane == 0) d_yl[r] = acc + bvoc[yv];
}

// ---------------- 5) combine partials: yp = logit[y] - logsumexp ----------------
__global__ __launch_bounds__(256) void k_final(float* __restrict__ out) {
    const int r = blockIdx.x;
    const int tid = threadIdx.x;
    __shared__ float sm[8];
    __shared__ float Mx;
    float m = -1e30f;
    for (int c = tid; c < NCH; c += 256) m = fmaxf(m, d_pmax[(long)r * NCH + c]);
    #pragma unroll
    for (int o = 16; o > 0; o >>= 1) m = fmaxf(m, __shfl_xor_sync(~0u, m, o));
    if ((tid & 31) == 0) sm[tid >> 5] = m;
    __syncthreads();
    if (tid == 0) {
        float a = -1e30f;
        #pragma unroll
        for (int w = 0; w < 8; w++) a = fmaxf(a, sm[w]);
        Mx = a;
    }
    __syncthreads();
    float s = 0.f;
    for (int c = tid; c < NCH; c += 256)
        s += d_psum[(long)r * NCH + c] * __expf(d_pmax[(long)r * NCH + c] - Mx);
    #pragma unroll
    for (int o = 16; o > 0; o >>= 1) s += __shfl_xor_sync(~0u, s, o);
    if ((tid & 31) == 0) sm[tid >> 5] = s;
    __syncthreads();
    if (tid == 0) {
        float a = 0.f;
        #pragma unroll
        for (int w = 0; w < 8; w++) a += sm[w];
        out[r] = d_yl[r] - (Mx + logf(a));
    }
}

// ---------------- launch ----------------
extern "C" void kernel_launch(void* const* d_in, const int* in_sizes, int n_in,
                              void* d_out, int out_size) {
    const int*   zi     = (const int*)d_in[0];
    const int*   y      = (const int*)d_in[1];
    const float* latent = (const float*)d_in[2];
    const float* W_tr   = (const float*)d_in[3];
    const float* b_tr   = (const float*)d_in[4];
    const float* Wv     = (const float*)d_in[5];
    const float* bvoc   = (const float*)d_in[6];
    const float* W_ext  = (const float*)d_in[7];
    const float* b_ext  = (const float*)d_in[8];
    float* out = (float*)d_out;

    k_convert<<<(VV * EE / 4 + 255) / 256, 256>>>(Wv);
    k_recur<<<BB * RCTA, RTHREADS>>>(zi, latent, W_tr, b_tr, W_ext, b_ext);
    k_ylogit<<<MM / 8, 256>>>(y, Wv, bvoc);
    k_logits<<<dim3(NCH, MM / BM), 256>>>(bvoc);
    k_final<<<MM, 256>>>(out);
}

// round 9
// speedup vs baseline: 3.6433x; 1.0104x over previous
#include <cuda_runtime.h>
#include <cuda_fp16.h>
#include <cstdint>
#include <mma.h>

// Problem constants
#define BB 32
#define TT 256
#define EE 512
#define SS 5
#define VV 32000
#define MM (BB*TT)   // 8192 rows of zs
// Recurrence config: 8 clusters x 8 CTAs, 4 batches per cluster
#define RCTA 8
#define NB 4
#define RROWS 64            // W rows per CTA
// GEMM tiling
#define BM 128
#define BN 256
#define BK 64
#define WPAD 72             // BK + 8 halves
#define NCH 500             // VV / 64 : per-64col chunks
#define STG_A (BM*WPAD)
#define STG_B (BN*WPAD)
#define SMEM_DYN (2*(STG_A+STG_B)*2)   // 110592 bytes

using namespace nvcuda;

// ---------------- scratch (device globals; no allocation allowed) ----------------
__device__ __half d_Wv[(size_t)VV*EE];     // 32 MB  fp16 vocab weights
__device__ __half d_zs[(size_t)MM*EE];     // 8 MB   fp16 emitted states
__device__ float  d_pmax[(size_t)MM*NCH];  // 16 MB  per-chunk max
__device__ float  d_psum[(size_t)MM*NCH];  // 16 MB  per-chunk sumexp
__device__ float  d_yl[MM];                // fp32 logit at label

// ---------------- 1) convert W_vocab fp32 -> fp16 ----------------
__global__ void k_convert(const float* __restrict__ Wv) {
    int i = blockIdx.x * blockDim.x + threadIdx.x;
    int n = (VV * EE) / 4;
    if (i < n) {
        float4 v = ((const float4*)Wv)[i];
        ((__half2*)d_Wv)[2*i]   = __floats2half2_rn(v.x, v.y);
        ((__half2*)d_Wv)[2*i+1] = __floats2half2_rn(v.z, v.w);
    }
}

// DSMEM store to a given cluster rank's smem at the same offset
__device__ __forceinline__ void st_cluster_f32(uint32_t laddr, int rank, float v) {
    uint32_t ra;
    asm volatile("mapa.shared::cluster.u32 %0, %1, %2;" : "=r"(ra) : "r"(laddr), "r"(rank));
    asm volatile("st.shared::cluster.f32 [%0], %1;" :: "r"(ra), "f"(v) : "memory");
}

// ---------------- 2) recurrence: 8-CTA cluster, 4 batches per cluster --------
// CTA rank owns W rows [rank*64, rank*64+64) and streams them ONCE per step
// for all 4 batches (chip W traffic 8MB/step, was 32MB). Ranks 0..3 each own
// one batch's norm/att/emit. zn broadcast + z_next scatter via DSMEM.
__global__ __launch_bounds__(256) __cluster_dims__(RCTA, 1, 1)
void k_recur(
    const int*   __restrict__ zi,
    const float* __restrict__ latent,
    const float* __restrict__ W_tr,
    const float* __restrict__ b_tr,
    const float* __restrict__ W_ext,
    const float* __restrict__ b_ext)
{
    __shared__ float zbuf[2][EE];        // own batch pre-norm state (ranks<4)
    __shared__ float zn_all[NB][EE];     // normalized state, all 4 batches
    __shared__ float lat[4][EE];         // own batch normalized latent rows 1..4
    __shared__ float We[SS][EE];
    __shared__ float btsl[RROWS];
    __shared__ float red[8][6];
    __shared__ float att[8];
    __shared__ float bcast;

    const int tid  = threadIdx.x;
    const int wid  = tid >> 5;
    const int lane = tid & 31;
    const int rank = blockIdx.x % RCTA;
    const int bat0 = (blockIdx.x / RCTA) * NB;
    const bool own = (rank < NB);
    const int myb  = bat0 + rank;

    if (tid < RROWS) btsl[tid] = b_tr[rank * RROWS + tid];

    if (own) {
        #pragma unroll
        for (int s = 0; s < SS; s++) {
            We[s][tid]       = W_ext[s * EE + tid];
            We[s][tid + 256] = W_ext[s * EE + tid + 256];
        }
        const long base = (long)zi[myb] * (SS * EE);
        for (int s = 0; s < SS; s++) {
            float x0 = latent[base + s * EE + tid];
            float x1 = latent[base + s * EE + tid + 256];
            float s1 = x0 + x1, s2 = x0 * x0 + x1 * x1;
            #pragma unroll
            for (int o = 16; o > 0; o >>= 1) {
                s1 += __shfl_xor_sync(~0u, s1, o);
                s2 += __shfl_xor_sync(~0u, s2, o);
            }
            if (lane == 0) { red[wid][0] = s1; red[wid][1] = s2; }
            __syncthreads();
            if (tid == 0) {
                float a = 0.f, c = 0.f;
                #pragma unroll
                for (int w = 0; w < 8; w++) { a += red[w][0]; c += red[w][1]; }
                float mean = a / EE;
                float var  = (c - EE * mean * mean) / (EE - 1);
                bcast = 0.113f / (1e-5f + sqrtf(fmaxf(var, 0.f)));
            }
            __syncthreads();
            float v0 = x0 * bcast, v1 = x1 * bcast;
            if (s == 0) { zbuf[0][tid] = v0; zbuf[0][tid + 256] = v1; }
            else        { lat[s-1][tid] = v0; lat[s-1][tid + 256] = v1; }
            __syncthreads();
        }
    }
    __syncthreads();

    const uint32_t znall_a = (uint32_t)__cvta_generic_to_shared(&zn_all[0][0]);
    const uint32_t zb_a[2] = {
        (uint32_t)__cvta_generic_to_shared(&zbuf[0][0]),
        (uint32_t)__cvta_generic_to_shared(&zbuf[1][0]) };

    for (int t = 0; t < TT; t++) {
        const int cur = t & 1;
        if (own) {
            const float z0 = zbuf[cur][tid], z1 = zbuf[cur][tid + 256];
            float s1 = z0 + z1, s2 = z0 * z0 + z1 * z1;
            #pragma unroll
            for (int o = 16; o > 0; o >>= 1) {
                s1 += __shfl_xor_sync(~0u, s1, o);
                s2 += __shfl_xor_sync(~0u, s2, o);
            }
            if (lane == 0) { red[wid][0] = s1; red[wid][1] = s2; }
            __syncthreads();
            if (tid == 0) {
                float a = 0.f, c = 0.f;
                #pragma unroll
                for (int w = 0; w < 8; w++) { a += red[w][0]; c += red[w][1]; }
                float mean = a / EE;
                float var  = (c - EE * mean * mean) / (EE - 1);
                bcast = 0.113f / (1e-5f + sqrtf(fmaxf(var, 0.f)));
            }
            __syncthreads();
            const float zn0 = z0 * bcast, zn1 = z1 * bcast;

            // broadcast zn (own batch -> slot 'rank') to all 8 CTAs; issued
            // early so the DSMEM drain overlaps att/emit below.
            {
                uint32_t la0 = znall_a + (uint32_t)((rank * EE + tid) * 4);
                uint32_t la1 = la0 + 256 * 4;
                #pragma unroll
                for (int pp = 0; pp < RCTA; pp++) {
                    st_cluster_f32(la0, pp, zn0);
                    st_cluster_f32(la1, pp, zn1);
                }
            }

            // att[s] = dot(zn, W_ext[s]) + b_ext[s]
            float p[SS];
            #pragma unroll
            for (int s = 0; s < SS; s++) p[s] = zn0 * We[s][tid] + zn1 * We[s][tid + 256];
            #pragma unroll
            for (int o = 16; o > 0; o >>= 1)
                #pragma unroll
                for (int s = 0; s < SS; s++) p[s] += __shfl_xor_sync(~0u, p[s], o);
            if (lane == 0)
                #pragma unroll
                for (int s = 0; s < SS; s++) red[wid][s] = p[s];
            __syncthreads();
            if (tid < SS) {
                float a = 0.f;
                #pragma unroll
                for (int w = 0; w < 8; w++) a += red[w][tid];
                att[tid] = a + b_ext[tid];
            }
            __syncthreads();

            // emit (own batch)
            float em0 = att[0] * zn0 + att[1] * lat[0][tid] + att[2] * lat[1][tid]
                      + att[3] * lat[2][tid] + att[4] * lat[3][tid];
            float em1 = att[0] * zn1 + att[1] * lat[0][tid+256] + att[2] * lat[1][tid+256]
                      + att[3] * lat[2][tid+256] + att[4] * lat[3][tid+256];
            __half* dst = d_zs + ((long)myb * TT + t) * EE;
            dst[tid]       = __float2half(em0);
            dst[tid + 256] = __float2half(em1);
        }

        asm volatile("barrier.cluster.arrive.aligned;" ::: "memory");
        asm volatile("barrier.cluster.wait.aligned;" ::: "memory");

        // matvec: own 64 W rows x 4 batches
        float4 zf[NB][4];
        #pragma unroll
        for (int b = 0; b < NB; b++) {
            const float4* zv = (const float4*)&zn_all[b][0];
            #pragma unroll
            for (int k = 0; k < 4; k++) zf[b][k] = zv[k * 32 + lane];
        }

        const uint32_t zbn = zb_a[cur ^ 1];
        const int rloc0 = wid * 8;
        #pragma unroll 2
        for (int rr = 0; rr < 8; rr++) {
            const int rloc = rloc0 + rr;
            const int r = rank * RROWS + rloc;
            const float4* Wr = (const float4*)(W_tr + (long)r * EE);
            float acc0 = 0.f, acc1 = 0.f, acc2 = 0.f, acc3 = 0.f;
            #pragma unroll
            for (int k = 0; k < 4; k++) {
                float4 w = Wr[k * 32 + lane];
                acc0 += w.x*zf[0][k].x + w.y*zf[0][k].y + w.z*zf[0][k].z + w.w*zf[0][k].w;
                acc1 += w.x*zf[1][k].x + w.y*zf[1][k].y + w.z*zf[1][k].z + w.w*zf[1][k].w;
                acc2 += w.x*zf[2][k].x + w.y*zf[2][k].y + w.z*zf[2][k].z + w.w*zf[2][k].w;
                acc3 += w.x*zf[3][k].x + w.y*zf[3][k].y + w.z*zf[3][k].z + w.w*zf[3][k].w;
            }
            #pragma unroll
            for (int o = 16; o > 0; o >>= 1) {
                acc0 += __shfl_xor_sync(~0u, acc0, o);
                acc1 += __shfl_xor_sync(~0u, acc1, o);
                acc2 += __shfl_xor_sync(~0u, acc2, o);
                acc3 += __shfl_xor_sync(~0u, acc3, o);
            }
            if (lane < NB) {
                float a = (lane == 0) ? acc0 : (lane == 1) ? acc1 : (lane == 2) ? acc2 : acc3;
                float v = 0.5f * (zn_all[lane][r] + a + btsl[rloc]);
                st_cluster_f32(zbn + (uint32_t)(r * 4), lane, v);
            }
        }

        asm volatile("barrier.cluster.arrive.aligned;" ::: "memory");
        asm volatile("barrier.cluster.wait.aligned;" ::: "memory");
    }
}

// ---------------- 3) fused vocab GEMM + per-chunk (max, sumexp) ----------------
// BM=128, BN=256, BK=64; 8 warps 2(m)x4(n); warp tile 64x64; cp.async 2-stage.
__device__ __forceinline__ void cp16(uint32_t dst, const void* src) {
    asm volatile("cp.async.cg.shared.global [%0], [%1], 16;" :: "r"(dst), "l"(src));
}

__global__ __launch_bounds__(256, 1) void k_logits(const float* __restrict__ bvoc) {
    extern __shared__ __half dynsm[];

    const int nch  = blockIdx.x;          // 256-col super chunk (125)
    const int mch  = blockIdx.y;          // 64 row chunks
    const int row0 = mch * BM;
    const int col0 = nch * BN;
    const int tid  = threadIdx.x;
    const int wid  = tid >> 5;            // 0..7
    const int lane = tid & 31;
    const int wm   = wid >> 2;            // 0..1
    const int wn   = wid & 3;             // 0..3

    const int seg = tid & 7;              // 16B segment in 64-half row
    const int lr0 = tid >> 3;             // 0..31

    wmma::fragment<wmma::accumulator, 16, 16, 16, float> cacc[4][4];
    #pragma unroll
    for (int i = 0; i < 4; i++)
        #pragma unroll
        for (int j = 0; j < 4; j++) wmma::fill_fragment(cacc[i][j], 0.f);

    auto load_stage = [&](int s, int k0) {
        __half* As = dynsm + s * (STG_A + STG_B);
        __half* Bs = As + STG_A;
        #pragma unroll
        for (int rr = 0; rr < 4; rr++) {
            int row = lr0 + rr * 32;
            cp16((uint32_t)__cvta_generic_to_shared(As + row * WPAD + seg * 8),
                 d_zs + ((long)(row0 + row)) * EE + k0 + seg * 8);
        }
        #pragma unroll
        for (int rr = 0; rr < 8; rr++) {
            int row = lr0 + rr * 32;
            cp16((uint32_t)__cvta_generic_to_shared(Bs + row * WPAD + seg * 8),
                 d_Wv + ((long)(col0 + row)) * EE + k0 + seg * 8);
        }
        asm volatile("cp.async.commit_group;");
    };

    load_stage(0, 0);
    for (int i = 0; i < 8; i++) {
        if (i < 7) {
            load_stage((i + 1) & 1, (i + 1) * BK);
            asm volatile("cp.async.wait_group 1;");
        } else {
            asm volatile("cp.async.wait_group 0;");
        }
        __syncthreads();
        __half* As = dynsm + (i & 1) * (STG_A + STG_B);
        __half* Bs = As + STG_A;
        #pragma unroll
        for (int kk = 0; kk < BK; kk += 16) {
            wmma::fragment<wmma::matrix_b, 16, 16, 16, __half, wmma::col_major> bf[4];
            #pragma unroll
            for (int j = 0; j < 4; j++)
                wmma::load_matrix_sync(bf[j], Bs + (wn * 64 + j * 16) * WPAD + kk, WPAD);
            #pragma unroll
            for (int i2 = 0; i2 < 4; i2++) {
                wmma::fragment<wmma::matrix_a, 16, 16, 16, __half, wmma::row_major> af;
                wmma::load_matrix_sync(af, As + (wm * 64 + i2 * 16) * WPAD + kk, WPAD);
                #pragma unroll
                for (int j = 0; j < 4; j++)
                    wmma::mma_sync(cacc[i2][j], af, bf[j], cacc[i2][j]);
            }
        }
        __syncthreads();
    }

    // epilogue: per-warp 16-row passes; each warp owns a 64-col chunk -> its
    // own (max,sumexp) partials. chunk index = nch*4 + wn, NCH = 500.
    float* scr = ((float*)dynsm) + wid * (16 * 68);
    const float* bv = bvoc + col0 + wn * 64 + (lane & 1) * 32;
    const int row = lane >> 1, hf = lane & 1;
    #pragma unroll
    for (int i2 = 0; i2 < 4; i2++) {
        #pragma unroll
        for (int j = 0; j < 4; j++)
            wmma::store_matrix_sync(scr + j * 16, cacc[i2][j], 68, wmma::mem_row_major);
        __syncwarp();
        const float* rp = scr + row * 68 + hf * 32;
        float mx = -1e30f;
        #pragma unroll 8
        for (int cc = 0; cc < 32; cc++) mx = fmaxf(mx, rp[cc] + bv[cc]);
        mx = fmaxf(mx, __shfl_xor_sync(~0u, mx, 1));
        float sum = 0.f;
        #pragma unroll 8
        for (int cc = 0; cc < 32; cc++) sum += __expf(rp[cc] + bv[cc] - mx);
        sum += __shfl_xor_sync(~0u, sum, 1);
        if (hf == 0) {
            const long grow = row0 + wm * 64 + i2 * 16 + row;
            d_pmax[grow * NCH + nch * 4 + wn] = mx;
            d_psum[grow * NCH + nch * 4 + wn] = sum;
        }
        __syncwarp();
    }
}

// ---------------- 4) exact logit at label (fp32 weights, fp16 zs) ----------------
__global__ void k_ylogit(const int* __restrict__ y,
                         const float* __restrict__ Wv,
                         const float* __restrict__ bvoc) {
    int r = blockIdx.x * 8 + (threadIdx.x >> 5);
    int lane = threadIdx.x & 31;
    int yv = y[r];
    const __half* z = d_zs + (long)r * EE;
    const float*  w = Wv + (long)yv * EE;
    float acc = 0.f;
    for (int e = lane; e < EE; e += 32)
        acc += __half2float(z[e]) * w[e];
    #pragma unroll
    for (int o = 16; o > 0; o >>= 1) acc += __shfl_xor_sync(~0u, acc, o);
    if (lane == 0) d_yl[r] = acc + bvoc[yv];
}

// ---------------- 5) combine partials: yp = logit[y] - logsumexp ----------------
__global__ __launch_bounds__(256) void k_final(float* __restrict__ out) {
    const int r = blockIdx.x;
    const int tid = threadIdx.x;
    __shared__ float sm[8];
    __shared__ float Mx;
    float m = -1e30f;
    for (int c = tid; c < NCH; c += 256) m = fmaxf(m, d_pmax[(long)r * NCH + c]);
    #pragma unroll
    for (int o = 16; o > 0; o >>= 1) m = fmaxf(m, __shfl_xor_sync(~0u, m, o));
    if ((tid & 31) == 0) sm[tid >> 5] = m;
    __syncthreads();
    if (tid == 0) {
        float a = -1e30f;
        #pragma unroll
        for (int w = 0; w < 8; w++) a = fmaxf(a, sm[w]);
        Mx = a;
    }
    __syncthreads();
    float s = 0.f;
    for (int c = tid; c < NCH; c += 256)
        s += d_psum[(long)r * NCH + c] * __expf(d_pmax[(long)r * NCH + c] - Mx);
    #pragma unroll
    for (int o = 16; o > 0; o >>= 1) s += __shfl_xor_sync(~0u, s, o);
    if ((tid & 31) == 0) sm[tid >> 5] = s;
    __syncthreads();
    if (tid == 0) {
        float a = 0.f;
        #pragma unroll
        for (int w = 0; w < 8; w++) a += sm[w];
        out[r] = d_yl[r] - (Mx + logf(a));
    }
}

// ---------------- launch ----------------
extern "C" void kernel_launch(void* const* d_in, const int* in_sizes, int n_in,
                              void* d_out, int out_size) {
    const int*   zi     = (const int*)d_in[0];
    const int*   y      = (const int*)d_in[1];
    const float* latent = (const float*)d_in[2];
    const float* W_tr   = (const float*)d_in[3];
    const float* b_tr   = (const float*)d_in[4];
    const float* Wv     = (const float*)d_in[5];
    const float* bvoc   = (const float*)d_in[6];
    const float* W_ext  = (const float*)d_in[7];
    const float* b_ext  = (const float*)d_in[8];
    float* out = (float*)d_out;

    cudaFuncSetAttribute(k_logits, cudaFuncAttributeMaxDynamicSharedMemorySize, SMEM_DYN);

    k_convert<<<(VV * EE / 4 + 255) / 256, 256>>>(Wv);
    k_recur<<<(BB / NB) * RCTA, 256>>>(zi, latent, W_tr, b_tr, W_ext, b_ext);
    k_ylogit<<<MM / 8, 256>>>(y, Wv, bvoc);
    k_logits<<<dim3(VV / BN, MM / BM), 256, SMEM_DYN>>>(bvoc);
    k_final<<<MM, 256>>>(out);
}

// round 11
// speedup vs baseline: 4.2097x; 1.1555x over previous
#include <cuda_runtime.h>
#include <cuda_fp16.h>
#include <cstdint>
#include <mma.h>

// Problem constants
#define BB 32
#define TT 256
#define EE 512
#define SS 5
#define VV 32000
#define MM (BB*TT)   // 8192 rows of zs
// Recurrence config: 8 clusters x 8 CTAs, 4 batches per cluster
#define RCTA 8
#define NB 4
#define RROWS 64            // W rows per CTA (resident in SMEM, fp32)
// GEMM tiling
#define BM 128
#define BN 256
#define BK 64
#define WPAD 72             // BK + 8 halves
#define NCH 500             // VV / 64 : per-64col chunks
#define STG_A (BM*WPAD)
#define STG_B (BN*WPAD)
#define NSTG 3
#define SMEM_GEMM (NSTG*(STG_A+STG_B)*2)   // 165888 bytes

// recurrence smem layout (floats)
#define OFF_W     0
#define OFF_ZBUF  (RROWS*EE)               // 32768
#define OFF_ZNALL (OFF_ZBUF + 2*EE)        // +1024
#define OFF_LAT   (OFF_ZNALL + NB*EE)      // +2048
#define OFF_WE    (OFF_LAT + 4*EE)         // +2048
#define OFF_BT    (OFF_WE + SS*EE)         // +2560
#define OFF_RED   (OFF_BT + RROWS)
#define OFF_ATT   (OFF_RED + 48)
#define OFF_BC    (OFF_ATT + 8)
#define SMEM_REC  ((OFF_BC + 4) * 4)       // bytes

using namespace nvcuda;

// ---------------- scratch (device globals; no allocation allowed) ----------------
__device__ __half d_Wv[(size_t)VV*EE];     // 32 MB  fp16 vocab weights
__device__ __half d_zs[(size_t)MM*EE];     // 8 MB   fp16 emitted states
__device__ float  d_pmax[(size_t)MM*NCH];  // 16 MB  per-chunk max
__device__ float  d_psum[(size_t)MM*NCH];  // 16 MB  per-chunk sumexp
__device__ float  d_yl[MM];                // fp32 logit at label

// ---------------- 1) convert W_vocab fp32 -> fp16 ----------------
__global__ void k_convert(const float* __restrict__ Wv) {
    int i = blockIdx.x * blockDim.x + threadIdx.x;
    int n = (VV * EE) / 4;
    if (i < n) {
        float4 v = ((const float4*)Wv)[i];
        ((__half2*)d_Wv)[2*i]   = __floats2half2_rn(v.x, v.y);
        ((__half2*)d_Wv)[2*i+1] = __floats2half2_rn(v.z, v.w);
    }
}

// DSMEM store to a given cluster rank's smem at the same offset
__device__ __forceinline__ void st_cluster_f32(uint32_t laddr, int rank, float v) {
    uint32_t ra;
    asm volatile("mapa.shared::cluster.u32 %0, %1, %2;" : "=r"(ra) : "r"(laddr), "r"(rank));
    asm volatile("st.shared::cluster.f32 [%0], %1;" :: "r"(ra), "f"(v) : "memory");
}

// ---------------- 2) recurrence: 8-CTA cluster, 4 batches, W in SMEM ---------
// CTA rank holds W rows [rank*64, rank*64+64) RESIDENT in smem (fp32, loaded
// once; 128KB). Per step the matvec reads W via LDS (29cyc) instead of L2
// (~250cyc), removing the L2 latency from the serial recurrence chain.
__global__ __launch_bounds__(256) __cluster_dims__(RCTA, 1, 1)
void k_recur(
    const int*   __restrict__ zi,
    const float* __restrict__ latent,
    const float* __restrict__ W_tr,
    const float* __restrict__ b_tr,
    const float* __restrict__ W_ext,
    const float* __restrict__ b_ext)
{
    extern __shared__ float sm[];
    float* Wsm    = sm + OFF_W;        // [RROWS][EE]
    float* zbuf   = sm + OFF_ZBUF;     // [2][EE]
    float* zn_all = sm + OFF_ZNALL;    // [NB][EE]
    float* lat    = sm + OFF_LAT;      // [4][EE]
    float* We     = sm + OFF_WE;       // [SS][EE]
    float* btsl   = sm + OFF_BT;       // [RROWS]
    float* red    = sm + OFF_RED;      // [8][6]
    float* att    = sm + OFF_ATT;      // [8]
    float* bcastp = sm + OFF_BC;

    const int tid  = threadIdx.x;
    const int wid  = tid >> 5;
    const int lane = tid & 31;
    const int rank = blockIdx.x % RCTA;
    const int bat0 = (blockIdx.x / RCTA) * NB;
    const bool own = (rank < NB);
    const int myb  = bat0 + rank;

    // load W slice once (coalesced float4)
    {
        const float4* Wg = (const float4*)(W_tr + (long)rank * RROWS * EE);
        float4* Wd = (float4*)Wsm;
        #pragma unroll
        for (int k = 0; k < (RROWS * EE / 4) / 256; k++)
            Wd[k * 256 + tid] = Wg[k * 256 + tid];
    }
    if (tid < RROWS) btsl[tid] = b_tr[rank * RROWS + tid];

    if (own) {
        #pragma unroll
        for (int s = 0; s < SS; s++) {
            We[s * EE + tid]       = W_ext[s * EE + tid];
            We[s * EE + tid + 256] = W_ext[s * EE + tid + 256];
        }
        const long base = (long)zi[myb] * (SS * EE);
        for (int s = 0; s < SS; s++) {
            float x0 = latent[base + s * EE + tid];
            float x1 = latent[base + s * EE + tid + 256];
            float s1 = x0 + x1, s2 = x0 * x0 + x1 * x1;
            #pragma unroll
            for (int o = 16; o > 0; o >>= 1) {
                s1 += __shfl_xor_sync(~0u, s1, o);
                s2 += __shfl_xor_sync(~0u, s2, o);
            }
            if (lane == 0) { red[wid * 6 + 0] = s1; red[wid * 6 + 1] = s2; }
            __syncthreads();
            if (tid == 0) {
                float a = 0.f, c = 0.f;
                #pragma unroll
                for (int w = 0; w < 8; w++) { a += red[w * 6 + 0]; c += red[w * 6 + 1]; }
                float mean = a / EE;
                float var  = (c - EE * mean * mean) / (EE - 1);
                bcastp[0] = 0.113f / (1e-5f + sqrtf(fmaxf(var, 0.f)));
            }
            __syncthreads();
            float bc = bcastp[0];
            float v0 = x0 * bc, v1 = x1 * bc;
            if (s == 0) { zbuf[tid] = v0; zbuf[tid + 256] = v1; }
            else        { lat[(s-1)*EE + tid] = v0; lat[(s-1)*EE + tid + 256] = v1; }
            __syncthreads();
        }
    }
    __syncthreads();

    const uint32_t znall_a = (uint32_t)__cvta_generic_to_shared(zn_all);
    const uint32_t zb_a[2] = {
        (uint32_t)__cvta_generic_to_shared(zbuf),
        (uint32_t)__cvta_generic_to_shared(zbuf + EE) };

    for (int t = 0; t < TT; t++) {
        const int cur = t & 1;
        if (own) {
            const float z0 = zbuf[cur * EE + tid], z1 = zbuf[cur * EE + tid + 256];
            float s1 = z0 + z1, s2 = z0 * z0 + z1 * z1;
            #pragma unroll
            for (int o = 16; o > 0; o >>= 1) {
                s1 += __shfl_xor_sync(~0u, s1, o);
                s2 += __shfl_xor_sync(~0u, s2, o);
            }
            if (lane == 0) { red[wid * 6 + 0] = s1; red[wid * 6 + 1] = s2; }
            __syncthreads();
            if (tid == 0) {
                float a = 0.f, c = 0.f;
                #pragma unroll
                for (int w = 0; w < 8; w++) { a += red[w * 6 + 0]; c += red[w * 6 + 1]; }
                float mean = a / EE;
                float var  = (c - EE * mean * mean) / (EE - 1);
                bcastp[0] = 0.113f / (1e-5f + sqrtf(fmaxf(var, 0.f)));
            }
            __syncthreads();
            const float bc = bcastp[0];
            const float zn0 = z0 * bc, zn1 = z1 * bc;

            // broadcast zn to slot 'rank' in all 8 CTAs (drain hides under att/emit)
            {
                uint32_t la0 = znall_a + (uint32_t)((rank * EE + tid) * 4);
                uint32_t la1 = la0 + 256 * 4;
                #pragma unroll
                for (int pp = 0; pp < RCTA; pp++) {
                    st_cluster_f32(la0, pp, zn0);
                    st_cluster_f32(la1, pp, zn1);
                }
            }

            // att[s] = dot(zn, W_ext[s]) + b_ext[s]
            float p[SS];
            #pragma unroll
            for (int s = 0; s < SS; s++) p[s] = zn0 * We[s*EE + tid] + zn1 * We[s*EE + tid + 256];
            #pragma unroll
            for (int o = 16; o > 0; o >>= 1)
                #pragma unroll
                for (int s = 0; s < SS; s++) p[s] += __shfl_xor_sync(~0u, p[s], o);
            if (lane == 0)
                #pragma unroll
                for (int s = 0; s < SS; s++) red[wid * 6 + s] = p[s];
            __syncthreads();
            if (tid < SS) {
                float a = 0.f;
                #pragma unroll
                for (int w = 0; w < 8; w++) a += red[w * 6 + tid];
                att[tid] = a + b_ext[tid];
            }
            __syncthreads();

            // emit (own batch)
            float em0 = att[0] * zn0 + att[1] * lat[tid] + att[2] * lat[EE + tid]
                      + att[3] * lat[2*EE + tid] + att[4] * lat[3*EE + tid];
            float em1 = att[0] * zn1 + att[1] * lat[tid+256] + att[2] * lat[EE + tid+256]
                      + att[3] * lat[2*EE + tid+256] + att[4] * lat[3*EE + tid+256];
            __half* dst = d_zs + ((long)myb * TT + t) * EE;
            dst[tid]       = __float2half(em0);
            dst[tid + 256] = __float2half(em1);
        }

        asm volatile("barrier.cluster.arrive.aligned;" ::: "memory");
        asm volatile("barrier.cluster.wait.aligned;" ::: "memory");

        // matvec from SMEM-resident W: own 64 rows x 4 batches
        float4 zf[NB][4];
        #pragma unroll
        for (int b = 0; b < NB; b++) {
            const float4* zv = (const float4*)(zn_all + b * EE);
            #pragma unroll
            for (int k = 0; k < 4; k++) zf[b][k] = zv[k * 32 + lane];
        }

        const uint32_t zbn = zb_a[cur ^ 1];
        const int rloc0 = wid * 8;
        #pragma unroll 2
        for (int rr = 0; rr < 8; rr++) {
            const int rloc = rloc0 + rr;
            const int r = rank * RROWS + rloc;
            const float4* Wr = (const float4*)(Wsm + (long)rloc * EE);
            float acc0 = 0.f, acc1 = 0.f, acc2 = 0.f, acc3 = 0.f;
            #pragma unroll
            for (int k = 0; k < 4; k++) {
                float4 w = Wr[k * 32 + lane];
                acc0 += w.x*zf[0][k].x + w.y*zf[0][k].y + w.z*zf[0][k].z + w.w*zf[0][k].w;
                acc1 += w.x*zf[1][k].x + w.y*zf[1][k].y + w.z*zf[1][k].z + w.w*zf[1][k].w;
                acc2 += w.x*zf[2][k].x + w.y*zf[2][k].y + w.z*zf[2][k].z + w.w*zf[2][k].w;
                acc3 += w.x*zf[3][k].x + w.y*zf[3][k].y + w.z*zf[3][k].z + w.w*zf[3][k].w;
            }
            #pragma unroll
            for (int o = 16; o > 0; o >>= 1) {
                acc0 += __shfl_xor_sync(~0u, acc0, o);
                acc1 += __shfl_xor_sync(~0u, acc1, o);
                acc2 += __shfl_xor_sync(~0u, acc2, o);
                acc3 += __shfl_xor_sync(~0u, acc3, o);
            }
            if (lane < NB) {
                float a = (lane == 0) ? acc0 : (lane == 1) ? acc1 : (lane == 2) ? acc2 : acc3;
                float v = 0.5f * (zn_all[lane * EE + r] + a + btsl[rloc]);
                st_cluster_f32(zbn + (uint32_t)(r * 4), lane, v);
            }
        }

        asm volatile("barrier.cluster.arrive.aligned;" ::: "memory");
        asm volatile("barrier.cluster.wait.aligned;" ::: "memory");
    }
}

// ---------------- 3) fused vocab GEMM + per-chunk (max, sumexp) ----------------
// BM=128, BN=256, BK=64; 8 warps 2(m)x4(n); warp tile 64x64; cp.async 3-stage.
__device__ __forceinline__ void cp16(uint32_t dst, const void* src) {
    asm volatile("cp.async.cg.shared.global [%0], [%1], 16;" :: "r"(dst), "l"(src));
}

__global__ __launch_bounds__(256, 1) void k_logits(const float* __restrict__ bvoc) {
    extern __shared__ __half dynsm[];

    const int nch  = blockIdx.x;          // 256-col super chunk (125)
    const int mch  = blockIdx.y;
    const int row0 = mch * BM;
    const int col0 = nch * BN;
    const int tid  = threadIdx.x;
    const int wid  = tid >> 5;
    const int lane = tid & 31;
    const int wm   = wid >> 2;            // 0..1
    const int wn   = wid & 3;             // 0..3

    const int seg = tid & 7;
    const int lr0 = tid >> 3;             // 0..31

    wmma::fragment<wmma::accumulator, 16, 16, 16, float> cacc[4][4];
    #pragma unroll
    for (int i = 0; i < 4; i++)
        #pragma unroll
        for (int j = 0; j < 4; j++) wmma::fill_fragment(cacc[i][j], 0.f);

    auto load_stage = [&](int s, int k0) {
        __half* As = dynsm + s * (STG_A + STG_B);
        __half* Bs = As + STG_A;
        #pragma unroll
        for (int rr = 0; rr < 4; rr++) {
            int row = lr0 + rr * 32;
            cp16((uint32_t)__cvta_generic_to_shared(As + row * WPAD + seg * 8),
                 d_zs + ((long)(row0 + row)) * EE + k0 + seg * 8);
        }
        #pragma unroll
        for (int rr = 0; rr < 8; rr++) {
            int row = lr0 + rr * 32;
            cp16((uint32_t)__cvta_generic_to_shared(Bs + row * WPAD + seg * 8),
                 d_Wv + ((long)(col0 + row)) * EE + k0 + seg * 8);
        }
        asm volatile("cp.async.commit_group;");
    };

    load_stage(0, 0);
    load_stage(1, BK);
    for (int i = 0; i < 8; i++) {
        if (i < 7) asm volatile("cp.async.wait_group 1;");
        else       asm volatile("cp.async.wait_group 0;");
        __syncthreads();
        __half* As = dynsm + (i % NSTG) * (STG_A + STG_B);
        __half* Bs = As + STG_A;
        #pragma unroll
        for (int kk = 0; kk < BK; kk += 16) {
            wmma::fragment<wmma::matrix_b, 16, 16, 16, __half, wmma::col_major> bf[4];
            #pragma unroll
            for (int j = 0; j < 4; j++)
                wmma::load_matrix_sync(bf[j], Bs + (wn * 64 + j * 16) * WPAD + kk, WPAD);
            #pragma unroll
            for (int i2 = 0; i2 < 4; i2++) {
                wmma::fragment<wmma::matrix_a, 16, 16, 16, __half, wmma::row_major> af;
                wmma::load_matrix_sync(af, As + (wm * 64 + i2 * 16) * WPAD + kk, WPAD);
                #pragma unroll
                for (int j = 0; j < 4; j++)
                    wmma::mma_sync(cacc[i2][j], af, bf[j], cacc[i2][j]);
            }
        }
        if (i + 2 < 8) load_stage((i + 2) % NSTG, (i + 2) * BK);
    }
    __syncthreads();

    // epilogue: per-warp 16-row passes; each warp owns a 64-col chunk.
    float* scr = ((float*)dynsm) + wid * (16 * 68);
    const float* bv = bvoc + col0 + wn * 64 + (lane & 1) * 32;
    const int row = lane >> 1, hf = lane & 1;
    #pragma unroll
    for (int i2 = 0; i2 < 4; i2++) {
        #pragma unroll
        for (int j = 0; j < 4; j++)
            wmma::store_matrix_sync(scr + j * 16, cacc[i2][j], 68, wmma::mem_row_major);
        __syncwarp();
        const float* rp = scr + row * 68 + hf * 32;
        float mx = -1e30f;
        #pragma unroll 8
        for (int cc = 0; cc < 32; cc++) mx = fmaxf(mx, rp[cc] + bv[cc]);
        mx = fmaxf(mx, __shfl_xor_sync(~0u, mx, 1));
        float sum = 0.f;
        #pragma unroll 8
        for (int cc = 0; cc < 32; cc++) sum += __expf(rp[cc] + bv[cc] - mx);
        sum += __shfl_xor_sync(~0u, sum, 1);
        if (hf == 0) {
            const long grow = row0 + wm * 64 + i2 * 16 + row;
            d_pmax[grow * NCH + nch * 4 + wn] = mx;
            d_psum[grow * NCH + nch * 4 + wn] = sum;
        }
        __syncwarp();
    }
}

// ---------------- 4) exact logit at label (fp32 weights, fp16 zs) ----------------
__global__ void k_ylogit(const int* __restrict__ y,
                         const float* __restrict__ Wv,
                         const float* __restrict__ bvoc) {
    int r = blockIdx.x * 8 + (threadIdx.x >> 5);
    int lane = threadIdx.x & 31;
    int yv = y[r];
    const __half* z = d_zs + (long)r * EE;
    const float*  w = Wv + (long)yv * EE;
    float acc = 0.f;
    for (int e = lane; e < EE; e += 32)
        acc += __half2float(z[e]) * w[e];
    #pragma unroll
    for (int o = 16; o > 0; o >>= 1) acc += __shfl_xor_sync(~0u, acc, o);
    if (lane == 0) d_yl[r] = acc + bvoc[yv];
}

// ---------------- 5) combine partials: yp = logit[y] - logsumexp ----------------
__global__ __launch_bounds__(256) void k_final(float* __restrict__ out) {
    const int r = blockIdx.x;
    const int tid = threadIdx.x;
    __shared__ float sm2[8];
    __shared__ float Mx;
    float m = -1e30f;
    for (int c = tid; c < NCH; c += 256) m = fmaxf(m, d_pmax[(long)r * NCH + c]);
    #pragma unroll
    for (int o = 16; o > 0; o >>= 1) m = fmaxf(m, __shfl_xor_sync(~0u, m, o));
    if ((tid & 31) == 0) sm2[tid >> 5] = m;
    __syncthreads();
    if (tid == 0) {
        float a = -1e30f;
        #pragma unroll
        for (int w = 0; w < 8; w++) a = fmaxf(a, sm2[w]);
        Mx = a;
    }
    __syncthreads();
    float s = 0.f;
    for (int c = tid; c < NCH; c += 256)
        s += d_psum[(long)r * NCH + c] * __expf(d_pmax[(long)r * NCH + c] - Mx);
    #pragma unroll
    for (int o = 16; o > 0; o >>= 1) s += __shfl_xor_sync(~0u, s, o);
    if ((tid & 31) == 0) sm2[tid >> 5] = s;
    __syncthreads();
    if (tid == 0) {
        float a = 0.f;
        #pragma unroll
        for (int w = 0; w < 8; w++) a += sm2[w];
        out[r] = d_yl[r] - (Mx + logf(a));
    }
}

// ---------------- launch ----------------
extern "C" void kernel_launch(void* const* d_in, const int* in_sizes, int n_in,
                              void* d_out, int out_size) {
    const int*   zi     = (const int*)d_in[0];
    const int*   y      = (const int*)d_in[1];
    const float* latent = (const float*)d_in[2];
    const float* W_tr   = (const float*)d_in[3];
    const float* b_tr   = (const float*)d_in[4];
    const float* Wv     = (const float*)d_in[5];
    const float* bvoc   = (const float*)d_in[6];
    const float* W_ext  = (const float*)d_in[7];
    const float* b_ext  = (const float*)d_in[8];
    float* out = (float*)d_out;

    cudaFuncSetAttribute(k_logits, cudaFuncAttributeMaxDynamicSharedMemorySize, SMEM_GEMM);
    cudaFuncSetAttribute(k_recur,  cudaFuncAttributeMaxDynamicSharedMemorySize, SMEM_REC);

    k_convert<<<(VV * EE / 4 + 255) / 256, 256>>>(Wv);
    k_recur<<<(BB / NB) * RCTA, 256, SMEM_REC>>>(zi, latent, W_tr, b_tr, W_ext, b_ext);
    k_ylogit<<<MM / 8, 256>>>(y, Wv, bvoc);
    k_logits<<<dim3(VV / BN, MM / BM), 256, SMEM_GEMM>>>(bvoc);
    k_final<<<MM, 256>>>(out);
}